// round 2
// baseline (speedup 1.0000x reference)
#include <cuda_runtime.h>
#include <cuda_fp16.h>
#include <cstdint>

#define EPSF 1e-8f

static constexpr int IN  = 256;
static constexpr int OUT = 256;
static constexpr int G   = 5;
static constexpr int K   = IN * G;   // 1280

static constexpr int BM = 128;
static constexpr int BN = 128;
static constexpr int BK = 80;        // 16 in-features * G
static constexpr int PK = 88;        // padded K stride (conflict-free ldmatrix)

// ---------------- device globals (scratch; no allocations allowed) ----------
__device__ unsigned int g_min_u;
__device__ unsigned int g_max_u;
__device__ __half g_W[OUT * K];      // coef*scale in fp16, [o][k] k-contiguous

// ordered-uint encoding of float for atomic min/max
__device__ __forceinline__ unsigned int f2ord(float f) {
    unsigned int u = __float_as_uint(f);
    return (u & 0x80000000u) ? ~u : (u | 0x80000000u);
}
__device__ __forceinline__ float ord2f(unsigned int u) {
    unsigned int b = (u & 0x80000000u) ? (u & 0x7FFFFFFFu) : ~u;
    return __uint_as_float(b);
}

// ---------------- kernel 0: reset reduction state ---------------------------
__global__ void init_kernel() {
    g_min_u = 0xFFFFFFFFu;
    g_max_u = 0x00000000u;
}

// ---------------- kernel 1: global min/max of x -----------------------------
__global__ void minmax_kernel(const float4* __restrict__ x4, int n4) {
    float lmin =  3.4e38f;
    float lmax = -3.4e38f;
    for (int i = blockIdx.x * blockDim.x + threadIdx.x; i < n4;
         i += gridDim.x * blockDim.x) {
        float4 v = x4[i];
        lmin = fminf(lmin, fminf(fminf(v.x, v.y), fminf(v.z, v.w)));
        lmax = fmaxf(lmax, fmaxf(fmaxf(v.x, v.y), fmaxf(v.z, v.w)));
    }
    // warp reduce
    #pragma unroll
    for (int off = 16; off > 0; off >>= 1) {
        lmin = fminf(lmin, __shfl_xor_sync(0xFFFFFFFFu, lmin, off));
        lmax = fmaxf(lmax, __shfl_xor_sync(0xFFFFFFFFu, lmax, off));
    }
    __shared__ float smin[8], smax[8];
    int warp = threadIdx.x >> 5, lane = threadIdx.x & 31;
    if (lane == 0) { smin[warp] = lmin; smax[warp] = lmax; }
    __syncthreads();
    if (warp == 0) {
        int nw = blockDim.x >> 5;
        lmin = (lane < nw) ? smin[lane] :  3.4e38f;
        lmax = (lane < nw) ? smax[lane] : -3.4e38f;
        #pragma unroll
        for (int off = 4; off > 0; off >>= 1) {
            lmin = fminf(lmin, __shfl_xor_sync(0xFFFFFFFFu, lmin, off));
            lmax = fmaxf(lmax, __shfl_xor_sync(0xFFFFFFFFu, lmax, off));
        }
        if (lane == 0) {
            atomicMin(&g_min_u, f2ord(lmin));
            atomicMax(&g_max_u, f2ord(lmax));
        }
    }
}

// ---------------- kernel 2: W = coef * scale -> fp16 ------------------------
__global__ void prep_kernel(const float* __restrict__ coef,
                            const float* __restrict__ scale) {
    int idx = blockIdx.x * blockDim.x + threadIdx.x;
    if (idx < OUT * K) {
        int o = idx / K;
        int r = idx % K;
        int i = r / G;
        g_W[idx] = __float2half(coef[idx] * scale[o * IN + i]);
    }
}

// ---------------- kernel 3: fused basis + GEMM ------------------------------
// out[b][o] = sum_k basis[b][k] * W[o][k] + bias[o]
// CTA tile 128x128, 8 warps of 32x64, mma.sync m16n8k16 fp16 -> fp32
__global__ __launch_bounds__(256, 2)
void kan_gemm_kernel(const float* __restrict__ x,
                     const float* __restrict__ grid,
                     const float* __restrict__ bias,
                     float* __restrict__ out) {
    __shared__ __align__(16) __half As[BM * PK];
    __shared__ __align__(16) __half Bs[BN * PK];
    __shared__ float bias_s[BN];
    __shared__ float grid_s[G];

    const int tid = threadIdx.x;
    const int bm0 = blockIdx.y * BM;
    const int bn0 = blockIdx.x * BN;

    if (tid < BN) bias_s[tid] = bias[bn0 + tid];
    if (tid < G)  grid_s[tid] = grid[tid];

    const float xmin = ord2f(g_min_u);
    const float xmax = ord2f(g_max_u);
    const float s2 = 2.0f / (xmax - xmin + EPSF);

    __syncthreads();   // grid_s / bias_s visible

    float acc[2][8][4];
    #pragma unroll
    for (int mi = 0; mi < 2; ++mi)
        #pragma unroll
        for (int nf = 0; nf < 8; ++nf)
            #pragma unroll
            for (int q = 0; q < 4; ++q) acc[mi][nf][q] = 0.0f;

    const int warp = tid >> 5, lane = tid & 31;
    const int wm = (warp >> 1) * 32;
    const int wn = (warp & 1) * 64;

    for (int ic = 0; ic < IN / 16; ++ic) {
        // ---- B tile: 128 rows x 80 halves (float4 copies) ----
        #pragma unroll
        for (int p = 0; p < 5; ++p) {
            int t = p * 256 + tid;           // 0..1279
            int row = t / 10;
            int c4 = t % 10;                 // float4 within the 80-half row
            const float4 v = *(const float4*)(g_W + (size_t)(bn0 + row) * K
                                              + ic * BK + c4 * 8);
            *(float4*)(Bs + row * PK + c4 * 8) = v;
        }
        // ---- A tile: compute basis on the fly ----
        #pragma unroll
        for (int p = 0; p < 8; ++p) {
            int t = p * 256 + tid;           // 0..2047
            int r = t >> 4;                  // local row
            int il = t & 15;                 // local in-feature
            float xv = x[(size_t)(bm0 + r) * IN + ic * 16 + il];
            float xn = (xv - xmin) * s2 - 1.0f;
            float bb[G];
            float bsum = 0.0f;
            #pragma unroll
            for (int g = 0; g < G; ++g) {
                float d = fabsf(xn - grid_s[g]);
                float v = (d < 1.0f) ? (1.0f - d * d * d) : 0.0f;
                bb[g] = v;
                bsum += v;
            }
            float inv = 1.0f / (bsum + EPSF);
            __half* dst = As + r * PK + il * G;
            #pragma unroll
            for (int g = 0; g < G; ++g) dst[g] = __float2half(bb[g] * inv);
        }
        __syncthreads();

        // ---- 5 k-steps of m16n8k16 ----
        #pragma unroll
        for (int ks = 0; ks < 5; ++ks) {
            const int k0 = ks * 16;
            uint32_t a[2][4];
            #pragma unroll
            for (int mi = 0; mi < 2; ++mi) {
                int row = wm + mi * 16 + (lane & 15);
                int col = k0 + (lane >> 4) * 8;
                uint32_t addr = (uint32_t)__cvta_generic_to_shared(
                    As + row * PK + col);
                asm volatile(
                    "ldmatrix.sync.aligned.m8n8.x4.shared.b16 "
                    "{%0,%1,%2,%3}, [%4];"
                    : "=r"(a[mi][0]), "=r"(a[mi][1]),
                      "=r"(a[mi][2]), "=r"(a[mi][3])
                    : "r"(addr));
            }
            uint32_t b[4][4];
            #pragma unroll
            for (int ni = 0; ni < 4; ++ni) {
                int row = wn + ni * 16 + (lane & 7) + ((lane >> 4) << 3);
                int col = k0 + (((lane >> 3) & 1) << 3);
                uint32_t addr = (uint32_t)__cvta_generic_to_shared(
                    Bs + row * PK + col);
                asm volatile(
                    "ldmatrix.sync.aligned.m8n8.x4.shared.b16 "
                    "{%0,%1,%2,%3}, [%4];"
                    : "=r"(b[ni][0]), "=r"(b[ni][1]),
                      "=r"(b[ni][2]), "=r"(b[ni][3])
                    : "r"(addr));
            }
            #pragma unroll
            for (int mi = 0; mi < 2; ++mi)
                #pragma unroll
                for (int nf = 0; nf < 8; ++nf) {
                    const uint32_t b0 = b[nf >> 1][(nf & 1) * 2];
                    const uint32_t b1 = b[nf >> 1][(nf & 1) * 2 + 1];
                    asm volatile(
                        "mma.sync.aligned.m16n8k16.row.col.f32.f16.f16.f32 "
                        "{%0,%1,%2,%3}, {%4,%5,%6,%7}, {%8,%9}, {%0,%1,%2,%3};"
                        : "+f"(acc[mi][nf][0]), "+f"(acc[mi][nf][1]),
                          "+f"(acc[mi][nf][2]), "+f"(acc[mi][nf][3])
                        : "r"(a[mi][0]), "r"(a[mi][1]),
                          "r"(a[mi][2]), "r"(a[mi][3]),
                          "r"(b0), "r"(b1));
                }
        }
        __syncthreads();
    }

    // ---- epilogue: + bias, fp32 store ----
    #pragma unroll
    for (int mi = 0; mi < 2; ++mi) {
        int r = bm0 + wm + mi * 16 + (lane >> 2);
        #pragma unroll
        for (int nf = 0; nf < 8; ++nf) {
            int cl = wn + nf * 8 + ((lane & 3) << 1);
            int c = bn0 + cl;
            float b0 = bias_s[cl];
            float b1 = bias_s[cl + 1];
            out[(size_t)r * OUT + c]           = acc[mi][nf][0] + b0;
            out[(size_t)r * OUT + c + 1]       = acc[mi][nf][1] + b1;
            out[(size_t)(r + 8) * OUT + c]     = acc[mi][nf][2] + b0;
            out[(size_t)(r + 8) * OUT + c + 1] = acc[mi][nf][3] + b1;
        }
    }
}

// ---------------------------------------------------------------------------
extern "C" void kernel_launch(void* const* d_in, const int* in_sizes, int n_in,
                              void* d_out, int out_size) {
    const float* x     = (const float*)d_in[0];
    const float* grid  = (const float*)d_in[1];
    const float* coef  = (const float*)d_in[2];
    const float* scale = (const float*)d_in[3];
    const float* bias  = (const float*)d_in[4];
    float* out = (float*)d_out;

    const int B = in_sizes[0] / IN;

    init_kernel<<<1, 1>>>();
    minmax_kernel<<<2048, 256>>>((const float4*)x, in_sizes[0] / 4);
    prep_kernel<<<(OUT * K + 255) / 256, 256>>>(coef, scale);

    dim3 g(OUT / BN, B / BM);
    kan_gemm_kernel<<<g, 256>>>(x, grid, bias, out);
}

// round 3
// speedup vs baseline: 1.2427x; 1.2427x over previous
#include <cuda_runtime.h>
#include <cuda_fp16.h>
#include <cstdint>

#define EPSF 1e-8f

static constexpr int IN  = 256;
static constexpr int OUT = 256;
static constexpr int G   = 5;
static constexpr int K   = IN * G;   // 1280

static constexpr int BM = 128;
static constexpr int BN = 128;
static constexpr int BK = 80;        // 16 in-features * G
static constexpr int PK = 88;        // padded K stride (conflict-free ldmatrix)

// ---------------- device globals (scratch; no allocations allowed) ----------
__device__ unsigned int g_min_u;
__device__ unsigned int g_max_u;
__device__ __half g_W[OUT * K];      // coef*scale in fp16, [o][k] k-contiguous

__device__ __forceinline__ unsigned int f2ord(float f) {
    unsigned int u = __float_as_uint(f);
    return (u & 0x80000000u) ? ~u : (u | 0x80000000u);
}
__device__ __forceinline__ float ord2f(unsigned int u) {
    unsigned int b = (u & 0x80000000u) ? (u & 0x7FFFFFFFu) : ~u;
    return __uint_as_float(b);
}

__device__ __forceinline__ void cp_async16(void* smem_dst, const void* gsrc) {
    uint32_t s = (uint32_t)__cvta_generic_to_shared(smem_dst);
    asm volatile("cp.async.cg.shared.global [%0], [%1], 16;\n"
                 :: "r"(s), "l"(gsrc));
}
#define CP_COMMIT() asm volatile("cp.async.commit_group;\n" ::: "memory")
#define CP_WAIT0()  asm volatile("cp.async.wait_group 0;\n" ::: "memory")

// ---------------- kernel 0: reset reduction state ---------------------------
__global__ void init_kernel() {
    g_min_u = 0xFFFFFFFFu;
    g_max_u = 0x00000000u;
}

// ---------------- kernel 1: global min/max of x -----------------------------
__global__ void minmax_kernel(const float4* __restrict__ x4, int n4) {
    float lmin =  3.4e38f;
    float lmax = -3.4e38f;
    for (int i = blockIdx.x * blockDim.x + threadIdx.x; i < n4;
         i += gridDim.x * blockDim.x) {
        float4 v = x4[i];
        lmin = fminf(lmin, fminf(fminf(v.x, v.y), fminf(v.z, v.w)));
        lmax = fmaxf(lmax, fmaxf(fmaxf(v.x, v.y), fmaxf(v.z, v.w)));
    }
    #pragma unroll
    for (int off = 16; off > 0; off >>= 1) {
        lmin = fminf(lmin, __shfl_xor_sync(0xFFFFFFFFu, lmin, off));
        lmax = fmaxf(lmax, __shfl_xor_sync(0xFFFFFFFFu, lmax, off));
    }
    __shared__ float smin[8], smax[8];
    int warp = threadIdx.x >> 5, lane = threadIdx.x & 31;
    if (lane == 0) { smin[warp] = lmin; smax[warp] = lmax; }
    __syncthreads();
    if (warp == 0) {
        int nw = blockDim.x >> 5;
        lmin = (lane < nw) ? smin[lane] :  3.4e38f;
        lmax = (lane < nw) ? smax[lane] : -3.4e38f;
        #pragma unroll
        for (int off = 4; off > 0; off >>= 1) {
            lmin = fminf(lmin, __shfl_xor_sync(0xFFFFFFFFu, lmin, off));
            lmax = fmaxf(lmax, __shfl_xor_sync(0xFFFFFFFFu, lmax, off));
        }
        if (lane == 0) {
            atomicMin(&g_min_u, f2ord(lmin));
            atomicMax(&g_max_u, f2ord(lmax));
        }
    }
}

// ---------------- kernel 2: W = coef * scale -> fp16 ------------------------
__global__ void prep_kernel(const float* __restrict__ coef,
                            const float* __restrict__ scale) {
    int idx = blockIdx.x * blockDim.x + threadIdx.x;
    if (idx < OUT * K) {
        int o = idx / K;
        int r = idx % K;
        int i = r / G;
        g_W[idx] = __float2half(coef[idx] * scale[o * IN + i]);
    }
}

// ---------------- kernel 3: fused basis + GEMM, depth-2 pipelined -----------
// smem layout (dynamic):
//   As[2][BM*PK] halves | Bs[2][BN*PK] halves | Xs[2][BM*16] floats | bias[BN]
__global__ __launch_bounds__(256, 2)
void kan_gemm_kernel(const float* __restrict__ x,
                     const float* __restrict__ grid,
                     const float* __restrict__ bias,
                     float* __restrict__ out) {
    extern __shared__ __align__(16) char smem_raw[];
    __half* As     = (__half*)smem_raw;                  // 2 * 11264 halves
    __half* Bs     = As + 2 * BM * PK;                   // 2 * 11264 halves
    float*  Xs     = (float*)(Bs + 2 * BN * PK);         // 2 * 2048 floats
    float*  bias_s = Xs + 2 * BM * 16;                   // 128 floats

    const int tid = threadIdx.x;
    const int bm0 = blockIdx.y * BM;
    const int bn0 = blockIdx.x * BN;

    if (tid < BN) bias_s[tid] = bias[bn0 + tid];

    float gr[G];
    #pragma unroll
    for (int g = 0; g < G; ++g) gr[g] = __ldg(grid + g);

    const float xmin = ord2f(g_min_u);
    const float xmax = ord2f(g_max_u);
    const float s2 = 2.0f / (xmax - xmin + EPSF);

    const int warp = tid >> 5, lane = tid & 31;
    const int wm = (warp >> 1) * 32;
    const int wn = (warp & 1) * 64;

    float acc[2][8][4];
    #pragma unroll
    for (int mi = 0; mi < 2; ++mi)
        #pragma unroll
        for (int nf = 0; nf < 8; ++nf)
            #pragma unroll
            for (int q = 0; q < 4; ++q) acc[mi][nf][q] = 0.0f;

    // ---- async loaders for chunk ic into buffer buf ----
    auto load_B = [&](int ic, int buf) {
        __half* dst = Bs + buf * BN * PK;
        #pragma unroll
        for (int q = 0; q < 5; ++q) {
            int idx = q * 256 + tid;        // 0..1279
            int row = idx / 10;
            int c4  = idx % 10;
            cp_async16(dst + row * PK + c4 * 8,
                       g_W + (size_t)(bn0 + row) * K + ic * BK + c4 * 8);
        }
    };
    auto load_X = [&](int ic, int buf) {
        float* dst = Xs + buf * BM * 16;
        #pragma unroll
        for (int q = 0; q < 2; ++q) {
            int idx = q * 256 + tid;        // 0..511
            int r = idx >> 2;
            int c = idx & 3;
            cp_async16(dst + r * 16 + c * 4,
                       x + (size_t)(bm0 + r) * IN + ic * 16 + c * 4);
        }
    };

    // prologue
    load_B(0, 0);
    load_X(0, 0);
    CP_COMMIT();

    for (int ic = 0; ic < IN / 16; ++ic) {
        const int cur = ic & 1;
        const int nxt = cur ^ 1;

        CP_WAIT0();
        __syncthreads();                    // Bs[cur], Xs[cur] visible

        if (ic + 1 < IN / 16) {
            load_B(ic + 1, nxt);
            load_X(ic + 1, nxt);
            CP_COMMIT();
        }

        // ---- basis from Xs[cur] -> As[cur] ----
        {
            const float* xs = Xs + cur * BM * 16;
            __half* as = As + cur * BM * PK;
            #pragma unroll
            for (int p = 0; p < 8; ++p) {
                int t = p * 256 + tid;      // 0..2047
                int r = t >> 4;
                int il = t & 15;
                float xn = (xs[r * 16 + il] - xmin) * s2 - 1.0f;
                float bb[G];
                float bsum = 0.0f;
                #pragma unroll
                for (int g = 0; g < G; ++g) {
                    float d = fabsf(xn - gr[g]);
                    float v = (d < 1.0f) ? (1.0f - d * d * d) : 0.0f;
                    bb[g] = v;
                    bsum += v;
                }
                float inv = 1.0f / (bsum + EPSF);
                __half* dst = as + r * PK + il * G;
                #pragma unroll
                for (int g = 0; g < G; ++g) dst[g] = __float2half(bb[g] * inv);
            }
        }
        __syncthreads();                    // As[cur] ready

        // ---- 5 k-steps of m16n8k16 ----
        const __half* as = As + cur * BM * PK;
        const __half* bs = Bs + cur * BN * PK;
        #pragma unroll
        for (int ks = 0; ks < 5; ++ks) {
            const int k0 = ks * 16;
            uint32_t a[2][4];
            #pragma unroll
            for (int mi = 0; mi < 2; ++mi) {
                int row = wm + mi * 16 + (lane & 15);
                int col = k0 + (lane >> 4) * 8;
                uint32_t addr = (uint32_t)__cvta_generic_to_shared(
                    as + row * PK + col);
                asm volatile(
                    "ldmatrix.sync.aligned.m8n8.x4.shared.b16 "
                    "{%0,%1,%2,%3}, [%4];"
                    : "=r"(a[mi][0]), "=r"(a[mi][1]),
                      "=r"(a[mi][2]), "=r"(a[mi][3])
                    : "r"(addr));
            }
            uint32_t b[4][4];
            #pragma unroll
            for (int ni = 0; ni < 4; ++ni) {
                int row = wn + ni * 16 + (lane & 7) + ((lane >> 4) << 3);
                int col = k0 + (((lane >> 3) & 1) << 3);
                uint32_t addr = (uint32_t)__cvta_generic_to_shared(
                    bs + row * PK + col);
                asm volatile(
                    "ldmatrix.sync.aligned.m8n8.x4.shared.b16 "
                    "{%0,%1,%2,%3}, [%4];"
                    : "=r"(b[ni][0]), "=r"(b[ni][1]),
                      "=r"(b[ni][2]), "=r"(b[ni][3])
                    : "r"(addr));
            }
            #pragma unroll
            for (int mi = 0; mi < 2; ++mi)
                #pragma unroll
                for (int nf = 0; nf < 8; ++nf) {
                    const uint32_t b0 = b[nf >> 1][(nf & 1) * 2];
                    const uint32_t b1 = b[nf >> 1][(nf & 1) * 2 + 1];
                    asm volatile(
                        "mma.sync.aligned.m16n8k16.row.col.f32.f16.f16.f32 "
                        "{%0,%1,%2,%3}, {%4,%5,%6,%7}, {%8,%9}, {%0,%1,%2,%3};"
                        : "+f"(acc[mi][nf][0]), "+f"(acc[mi][nf][1]),
                          "+f"(acc[mi][nf][2]), "+f"(acc[mi][nf][3])
                        : "r"(a[mi][0]), "r"(a[mi][1]),
                          "r"(a[mi][2]), "r"(a[mi][3]),
                          "r"(b0), "r"(b1));
                }
        }
        __syncthreads();                    // done with cur buffers
    }

    // ---- epilogue: + bias, float2 stores ----
    #pragma unroll
    for (int mi = 0; mi < 2; ++mi) {
        int r = bm0 + wm + mi * 16 + (lane >> 2);
        #pragma unroll
        for (int nf = 0; nf < 8; ++nf) {
            int cl = wn + nf * 8 + ((lane & 3) << 1);
            int c = bn0 + cl;
            float b0 = bias_s[cl];
            float b1 = bias_s[cl + 1];
            float2 v0 = make_float2(acc[mi][nf][0] + b0, acc[mi][nf][1] + b1);
            float2 v1 = make_float2(acc[mi][nf][2] + b0, acc[mi][nf][3] + b1);
            *(float2*)(out + (size_t)r * OUT + c) = v0;
            *(float2*)(out + (size_t)(r + 8) * OUT + c) = v1;
        }
    }
}

// ---------------------------------------------------------------------------
static constexpr int SMEM_BYTES =
    2 * BM * PK * 2 + 2 * BN * PK * 2 + 2 * BM * 16 * 4 + BN * 4;

extern "C" void kernel_launch(void* const* d_in, const int* in_sizes, int n_in,
                              void* d_out, int out_size) {
    const float* x     = (const float*)d_in[0];
    const float* grid  = (const float*)d_in[1];
    const float* coef  = (const float*)d_in[2];
    const float* scale = (const float*)d_in[3];
    const float* bias  = (const float*)d_in[4];
    float* out = (float*)d_out;

    const int B = in_sizes[0] / IN;

    cudaFuncSetAttribute(kan_gemm_kernel,
                         cudaFuncAttributeMaxDynamicSharedMemorySize,
                         SMEM_BYTES);

    init_kernel<<<1, 1>>>();
    minmax_kernel<<<2048, 256>>>((const float4*)x, in_sizes[0] / 4);
    prep_kernel<<<(OUT * K + 255) / 256, 256>>>(coef, scale);

    dim3 g(OUT / BN, B / BM);
    kan_gemm_kernel<<<g, 256, SMEM_BYTES>>>(x, grid, bias, out);
}

// round 4
// speedup vs baseline: 1.2820x; 1.0316x over previous
#include <cuda_runtime.h>
#include <cuda_fp16.h>
#include <cstdint>

#define EPSF 1e-8f

static constexpr int IN  = 256;
static constexpr int OUT = 256;
static constexpr int G   = 5;
static constexpr int K   = IN * G;    // 1280
static constexpr int BQ  = 32768;     // batch (fixed per problem)

static constexpr int BM = 128;
static constexpr int BN = 128;
static constexpr int BK = 64;         // k-chunk (halves) = 128 bytes/row
static constexpr int STAGES = 3;
static constexpr int NCH = K / BK;    // 20

// ---------------- device globals (scratch; no allocations allowed) ----------
__device__ unsigned int g_min_u;
__device__ unsigned int g_max_u;
__device__ __half g_W[OUT * K];              // coef*scale fp16, [o][k]
__device__ __half g_A[(size_t)BQ * K];       // basis fp16, [b][k]

__device__ __forceinline__ unsigned int f2ord(float f) {
    unsigned int u = __float_as_uint(f);
    return (u & 0x80000000u) ? ~u : (u | 0x80000000u);
}
__device__ __forceinline__ float ord2f(unsigned int u) {
    unsigned int b = (u & 0x80000000u) ? (u & 0x7FFFFFFFu) : ~u;
    return __uint_as_float(b);
}

__device__ __forceinline__ void cp_async16(void* smem_dst, const void* gsrc) {
    uint32_t s = (uint32_t)__cvta_generic_to_shared(smem_dst);
    asm volatile("cp.async.cg.shared.global [%0], [%1], 16;\n"
                 :: "r"(s), "l"(gsrc));
}
#define CP_COMMIT() asm volatile("cp.async.commit_group;\n" ::: "memory")
#define CP_WAIT(n)  asm volatile("cp.async.wait_group %0;\n" :: "n"(n) : "memory")

// XOR swizzle for 128-byte rows (8x16B chunks), conflict-free ldmatrix
__device__ __forceinline__ uint32_t swz(uint32_t byte_off) {
    return byte_off ^ ((byte_off >> 3) & 0x70);
}

// ---------------- kernel 0: reset reduction state ---------------------------
__global__ void init_kernel() {
    g_min_u = 0xFFFFFFFFu;
    g_max_u = 0x00000000u;
}

// ---------------- kernel 1: global min/max of x -----------------------------
__global__ void minmax_kernel(const float4* __restrict__ x4, int n4) {
    float lmin =  3.4e38f;
    float lmax = -3.4e38f;
    for (int i = blockIdx.x * blockDim.x + threadIdx.x; i < n4;
         i += gridDim.x * blockDim.x) {
        float4 v = x4[i];
        lmin = fminf(lmin, fminf(fminf(v.x, v.y), fminf(v.z, v.w)));
        lmax = fmaxf(lmax, fmaxf(fmaxf(v.x, v.y), fmaxf(v.z, v.w)));
    }
    #pragma unroll
    for (int off = 16; off > 0; off >>= 1) {
        lmin = fminf(lmin, __shfl_xor_sync(0xFFFFFFFFu, lmin, off));
        lmax = fmaxf(lmax, __shfl_xor_sync(0xFFFFFFFFu, lmax, off));
    }
    __shared__ float smin[8], smax[8];
    int warp = threadIdx.x >> 5, lane = threadIdx.x & 31;
    if (lane == 0) { smin[warp] = lmin; smax[warp] = lmax; }
    __syncthreads();
    if (warp == 0) {
        int nw = blockDim.x >> 5;
        lmin = (lane < nw) ? smin[lane] :  3.4e38f;
        lmax = (lane < nw) ? smax[lane] : -3.4e38f;
        #pragma unroll
        for (int off = 4; off > 0; off >>= 1) {
            lmin = fminf(lmin, __shfl_xor_sync(0xFFFFFFFFu, lmin, off));
            lmax = fmaxf(lmax, __shfl_xor_sync(0xFFFFFFFFu, lmax, off));
        }
        if (lane == 0) {
            atomicMin(&g_min_u, f2ord(lmin));
            atomicMax(&g_max_u, f2ord(lmax));
        }
    }
}

// ---------------- kernel 2: W = coef * scale -> fp16 ------------------------
__global__ void prep_kernel(const float* __restrict__ coef,
                            const float* __restrict__ scale) {
    int idx = blockIdx.x * blockDim.x + threadIdx.x;
    if (idx < OUT * K) {
        int o = idx / K;
        int r = idx % K;
        int i = r / G;
        g_W[idx] = __float2half(coef[idx] * scale[o * IN + i]);
    }
}

// ---------------- kernel 3: basis(x) -> g_A (fp16, coalesced) ---------------
// block: 256 threads handles 16 rows; smem-staged so global writes are float4
static constexpr int BR = 16;   // rows per block
__global__ __launch_bounds__(256)
void basis_kernel(const float* __restrict__ x, const float* __restrict__ grid) {
    __shared__ __align__(16) __half as[BR * K];   // 16*1280*2 = 40KB

    const int tid = threadIdx.x;
    const int r0 = blockIdx.x * BR;

    float gr[G];
    #pragma unroll
    for (int g = 0; g < G; ++g) gr[g] = __ldg(grid + g);

    const float xmin = ord2f(g_min_u);
    const float xmax = ord2f(g_max_u);
    const float s2 = 2.0f / (xmax - xmin + EPSF);

    // compute phase: 16*256 = 4096 elements, 16 per thread, coalesced x reads
    #pragma unroll
    for (int e = 0; e < BR; ++e) {
        int idx = e * 256 + tid;
        int r = idx >> 8;          // local row
        int i = idx & 255;         // in-feature
        float xv = x[(size_t)(r0 + r) * IN + i];
        float xn = (xv - xmin) * s2 - 1.0f;
        float bb[G];
        float bsum = 0.0f;
        #pragma unroll
        for (int g = 0; g < G; ++g) {
            float d = fabsf(xn - gr[g]);
            float v = (d < 1.0f) ? (1.0f - d * d * d) : 0.0f;
            bb[g] = v;
            bsum += v;
        }
        float inv = 1.0f / (bsum + EPSF);
        __half* dst = as + r * K + i * G;
        #pragma unroll
        for (int g = 0; g < G; ++g) dst[g] = __float2half(bb[g] * inv);
    }
    __syncthreads();

    // write phase: 16 rows * 2560B = 2560 float4, 10 per thread, coalesced
    const float4* src = (const float4*)as;
    float4* dst = (float4*)(g_A + (size_t)r0 * K);
    #pragma unroll
    for (int q = 0; q < 10; ++q) dst[q * 256 + tid] = src[q * 256 + tid];
}

// ---------------- kernel 4: pure fp16 GEMM, 3-stage cp.async pipeline -------
// C[b][o] = sum_k A[b][k] * W[o][k] + bias[o]
__global__ __launch_bounds__(256, 2)
void kan_gemm_kernel(const float* __restrict__ bias, float* __restrict__ out) {
    extern __shared__ __align__(16) char smem_raw[];
    // As[STAGES][BM*BK], Bs[STAGES][BN*BK] halves (swizzled rows of 128B)
    __half* As     = (__half*)smem_raw;
    __half* Bs     = As + STAGES * BM * BK;
    float*  bias_s = (float*)(Bs + STAGES * BN * BK);

    const int tid = threadIdx.x;
    const int bm0 = blockIdx.y * BM;
    const int bn0 = blockIdx.x * BN;

    if (tid < BN) bias_s[tid] = bias[bn0 + tid];

    const int warp = tid >> 5, lane = tid & 31;
    const int wm = (warp >> 1) * 32;
    const int wn = (warp & 1) * 64;

    float acc[2][8][4];
    #pragma unroll
    for (int mi = 0; mi < 2; ++mi)
        #pragma unroll
        for (int nf = 0; nf < 8; ++nf)
            #pragma unroll
            for (int q = 0; q < 4; ++q) acc[mi][nf][q] = 0.0f;

    auto load_stage = [&](int ic, int st) {
        char* adst = (char*)(As + st * BM * BK);
        char* bdst = (char*)(Bs + st * BN * BK);
        #pragma unroll
        for (int q = 0; q < 4; ++q) {
            int idx = q * 256 + tid;       // 0..1023
            int row = idx >> 3;
            int c   = idx & 7;             // 16B chunk in 128B row
            uint32_t so = swz(row * 128 + c * 16);
            cp_async16(adst + so,
                       g_A + (size_t)(bm0 + row) * K + ic * BK + c * 8);
            cp_async16(bdst + so,
                       g_W + (size_t)(bn0 + row) * K + ic * BK + c * 8);
        }
        CP_COMMIT();
    };

    // prologue: fill STAGES-1 stages
    #pragma unroll
    for (int s = 0; s < STAGES - 1; ++s) load_stage(s, s);

    for (int ic = 0; ic < NCH; ++ic) {
        CP_WAIT(STAGES - 2);
        __syncthreads();

        if (ic + STAGES - 1 < NCH)
            load_stage(ic + STAGES - 1, (ic + STAGES - 1) % STAGES);

        const int st = ic % STAGES;
        const char* as = (const char*)(As + st * BM * BK);
        const char* bs = (const char*)(Bs + st * BN * BK);

        #pragma unroll
        for (int ks = 0; ks < 4; ++ks) {
            const int k0 = ks * 16;
            uint32_t a[2][4];
            #pragma unroll
            for (int mi = 0; mi < 2; ++mi) {
                int row = wm + mi * 16 + (lane & 15);
                int cb  = k0 * 2 + (lane >> 4) * 16;   // byte col
                uint32_t addr = (uint32_t)__cvta_generic_to_shared(
                    as + swz(row * 128 + cb));
                asm volatile(
                    "ldmatrix.sync.aligned.m8n8.x4.shared.b16 "
                    "{%0,%1,%2,%3}, [%4];"
                    : "=r"(a[mi][0]), "=r"(a[mi][1]),
                      "=r"(a[mi][2]), "=r"(a[mi][3])
                    : "r"(addr));
            }
            uint32_t b[4][4];
            #pragma unroll
            for (int ni = 0; ni < 4; ++ni) {
                int row = wn + ni * 16 + (lane & 7) + ((lane >> 4) << 3);
                int cb  = k0 * 2 + (((lane >> 3) & 1) << 4);
                uint32_t addr = (uint32_t)__cvta_generic_to_shared(
                    bs + swz(row * 128 + cb));
                asm volatile(
                    "ldmatrix.sync.aligned.m8n8.x4.shared.b16 "
                    "{%0,%1,%2,%3}, [%4];"
                    : "=r"(b[ni][0]), "=r"(b[ni][1]),
                      "=r"(b[ni][2]), "=r"(b[ni][3])
                    : "r"(addr));
            }
            #pragma unroll
            for (int mi = 0; mi < 2; ++mi)
                #pragma unroll
                for (int nf = 0; nf < 8; ++nf) {
                    const uint32_t b0 = b[nf >> 1][(nf & 1) * 2];
                    const uint32_t b1 = b[nf >> 1][(nf & 1) * 2 + 1];
                    asm volatile(
                        "mma.sync.aligned.m16n8k16.row.col.f32.f16.f16.f32 "
                        "{%0,%1,%2,%3}, {%4,%5,%6,%7}, {%8,%9}, {%0,%1,%2,%3};"
                        : "+f"(acc[mi][nf][0]), "+f"(acc[mi][nf][1]),
                          "+f"(acc[mi][nf][2]), "+f"(acc[mi][nf][3])
                        : "r"(a[mi][0]), "r"(a[mi][1]),
                          "r"(a[mi][2]), "r"(a[mi][3]),
                          "r"(b0), "r"(b1));
                }
        }
        __syncthreads();
    }

    // epilogue: + bias, float2 stores
    #pragma unroll
    for (int mi = 0; mi < 2; ++mi) {
        int r = bm0 + wm + mi * 16 + (lane >> 2);
        #pragma unroll
        for (int nf = 0; nf < 8; ++nf) {
            int cl = wn + nf * 8 + ((lane & 3) << 1);
            int c = bn0 + cl;
            float b0 = bias_s[cl];
            float b1 = bias_s[cl + 1];
            float2 v0 = make_float2(acc[mi][nf][0] + b0, acc[mi][nf][1] + b1);
            float2 v1 = make_float2(acc[mi][nf][2] + b0, acc[mi][nf][3] + b1);
            *(float2*)(out + (size_t)r * OUT + c) = v0;
            *(float2*)(out + (size_t)(r + 8) * OUT + c) = v1;
        }
    }
}

// ---------------------------------------------------------------------------
static constexpr int SMEM_BYTES =
    STAGES * BM * BK * 2 + STAGES * BN * BK * 2 + BN * 4;

extern "C" void kernel_launch(void* const* d_in, const int* in_sizes, int n_in,
                              void* d_out, int out_size) {
    const float* x     = (const float*)d_in[0];
    const float* grid  = (const float*)d_in[1];
    const float* coef  = (const float*)d_in[2];
    const float* scale = (const float*)d_in[3];
    const float* bias  = (const float*)d_in[4];
    float* out = (float*)d_out;

    const int B = in_sizes[0] / IN;

    cudaFuncSetAttribute(kan_gemm_kernel,
                         cudaFuncAttributeMaxDynamicSharedMemorySize,
                         SMEM_BYTES);

    init_kernel<<<1, 1>>>();
    minmax_kernel<<<2048, 256>>>((const float4*)x, in_sizes[0] / 4);
    prep_kernel<<<(OUT * K + 255) / 256, 256>>>(coef, scale);
    basis_kernel<<<B / BR, 256>>>(x, grid);

    dim3 g(OUT / BN, B / BM);
    kan_gemm_kernel<<<g, 256, SMEM_BYTES>>>(bias, out);
}

// round 7
// speedup vs baseline: 1.2855x; 1.0028x over previous
#include <cuda_runtime.h>
#include <cuda_fp16.h>
#include <cstdint>

#define EPSF 1e-8f

static constexpr int IN  = 256;
static constexpr int OUT = 256;
static constexpr int G   = 5;
static constexpr int K   = IN * G;    // 1280
static constexpr int BQ  = 32768;

// GEMM tiling
static constexpr int BM = 128;
static constexpr int BN = 256;        // = OUT (full width)
static constexpr int BK = 64;         // halves per chunk = 128B rows
static constexpr int NCH = K / BK;    // 20
static constexpr int STAGES = 4;
static constexpr int STG_BYTES = (BM + BN) * 128;   // 48KB per stage

// ---------------- device globals (scratch; no allocations allowed) ----------
__device__ unsigned int g_min_u;
__device__ unsigned int g_max_u;
__device__ __half g_W[OUT * K];              // coef*scale fp16, [o][k]
__device__ __half g_A[(size_t)BQ * K];       // basis fp16, [b][k]

__device__ __forceinline__ unsigned int f2ord(float f) {
    unsigned int u = __float_as_uint(f);
    return (u & 0x80000000u) ? ~u : (u | 0x80000000u);
}
__device__ __forceinline__ float ord2f(unsigned int u) {
    unsigned int b = (u & 0x80000000u) ? (u & 0x7FFFFFFFu) : ~u;
    return __uint_as_float(b);
}

__device__ __forceinline__ void cp_async16(void* smem_dst, const void* gsrc) {
    uint32_t s = (uint32_t)__cvta_generic_to_shared(smem_dst);
    asm volatile("cp.async.cg.shared.global [%0], [%1], 16;\n"
                 :: "r"(s), "l"(gsrc));
}
#define CP_COMMIT() asm volatile("cp.async.commit_group;\n" ::: "memory")
#define CP_WAIT(n)  asm volatile("cp.async.wait_group %0;\n" :: "n"(n) : "memory")

// XOR swizzle for 128-byte rows (8x16B chunks), conflict-free ldmatrix
__device__ __forceinline__ uint32_t swz(uint32_t b) {
    return b ^ ((b >> 3) & 0x70);
}

// ---------------- kernel 0: reset reduction state ---------------------------
__global__ void init_kernel() {
    g_min_u = 0xFFFFFFFFu;
    g_max_u = 0x00000000u;
}

// ---------------- kernel 1: global min/max of x -----------------------------
__global__ void minmax_kernel(const float4* __restrict__ x4, int n4) {
    float lmin =  3.4e38f;
    float lmax = -3.4e38f;
    for (int i = blockIdx.x * blockDim.x + threadIdx.x; i < n4;
         i += gridDim.x * blockDim.x) {
        float4 v = x4[i];
        lmin = fminf(lmin, fminf(fminf(v.x, v.y), fminf(v.z, v.w)));
        lmax = fmaxf(lmax, fmaxf(fmaxf(v.x, v.y), fmaxf(v.z, v.w)));
    }
    #pragma unroll
    for (int off = 16; off > 0; off >>= 1) {
        lmin = fminf(lmin, __shfl_xor_sync(0xFFFFFFFFu, lmin, off));
        lmax = fmaxf(lmax, __shfl_xor_sync(0xFFFFFFFFu, lmax, off));
    }
    __shared__ float smin[8], smax[8];
    int warp = threadIdx.x >> 5, lane = threadIdx.x & 31;
    if (lane == 0) { smin[warp] = lmin; smax[warp] = lmax; }
    __syncthreads();
    if (warp == 0) {
        int nw = blockDim.x >> 5;
        lmin = (lane < nw) ? smin[lane] :  3.4e38f;
        lmax = (lane < nw) ? smax[lane] : -3.4e38f;
        #pragma unroll
        for (int off = 4; off > 0; off >>= 1) {
            lmin = fminf(lmin, __shfl_xor_sync(0xFFFFFFFFu, lmin, off));
            lmax = fmaxf(lmax, __shfl_xor_sync(0xFFFFFFFFu, lmax, off));
        }
        if (lane == 0) {
            atomicMin(&g_min_u, f2ord(lmin));
            atomicMax(&g_max_u, f2ord(lmax));
        }
    }
}

// ---------------- kernel 2: W = coef * scale -> fp16 ------------------------
__global__ void prep_kernel(const float* __restrict__ coef,
                            const float* __restrict__ scale) {
    int idx = blockIdx.x * blockDim.x + threadIdx.x;
    if (idx < OUT * K) {
        int o = idx / K;
        int r = idx % K;
        int i = r / G;
        g_W[idx] = __float2half(coef[idx] * scale[o * IN + i]);
    }
}

// ---------------- kernel 3: basis(x) -> g_A, register-only ------------------
// 8 warps/block; warp handles one row; lane handles 8 consecutive in-features
// -> 40 halves = 80 contiguous bytes = 5 aligned float4 stores. No SMEM.
__global__ __launch_bounds__(256)
void basis_kernel(const float* __restrict__ x, const float* __restrict__ grid) {
    const int warp = threadIdx.x >> 5, lane = threadIdx.x & 31;
    const int row = blockIdx.x * 8 + warp;

    float gr[G];
    #pragma unroll
    for (int g = 0; g < G; ++g) gr[g] = __ldg(grid + g);

    const float xmin = ord2f(g_min_u);
    const float xmax = ord2f(g_max_u);
    const float s2 = 2.0f / (xmax - xmin + EPSF);

    const float4* xr = (const float4*)(x + (size_t)row * IN + lane * 8);
    float4 v0 = xr[0], v1 = xr[1];
    float xs[8] = {v0.x, v0.y, v0.z, v0.w, v1.x, v1.y, v1.z, v1.w};

    union { __half h[40]; uint4 u[5]; } buf;
    #pragma unroll
    for (int j = 0; j < 8; ++j) {
        float xn = (xs[j] - xmin) * s2 - 1.0f;
        float bb[G];
        float bsum = 0.0f;
        #pragma unroll
        for (int g = 0; g < G; ++g) {
            float d = fabsf(xn - gr[g]);
            float v = (d < 1.0f) ? (1.0f - d * d * d) : 0.0f;
            bb[g] = v;
            bsum += v;
        }
        float inv = 1.0f / (bsum + EPSF);
        #pragma unroll
        for (int g = 0; g < G; ++g)
            buf.h[j * G + g] = __float2half(bb[g] * inv);
    }
    uint4* dst = (uint4*)(g_A + (size_t)row * K + lane * 40);
    #pragma unroll
    for (int q = 0; q < 5; ++q) dst[q] = buf.u[q];
}

// ---------------- kernel 4: fp16 GEMM, 512 thr, 4-stage pipeline ------------
// C[b][o] = sum_k A[b][k] * W[o][k] + bias[o]
// 16 warps, warp tile 32x64: m-group = warp>>2 (4 x 32), n-group = warp&3 (4 x 64)
__global__ __launch_bounds__(512, 1)
void kan_gemm_kernel(const float* __restrict__ bias, float* __restrict__ out) {
    extern __shared__ __align__(16) char smem_raw[];
    float* bias_s = (float*)smem_raw;              // 256 floats
    char* stg = smem_raw + 1024;                   // STAGES x 48KB

    const int tid = threadIdx.x;
    const int bm0 = blockIdx.x * BM;

    if (tid < BN) bias_s[tid] = bias[tid];

    const int warp = tid >> 5, lane = tid & 31;
    const int wm = (warp >> 2) * 32;
    const int wn = (warp & 3) * 64;

    float acc[2][8][4];
    #pragma unroll
    for (int mi = 0; mi < 2; ++mi)
        #pragma unroll
        for (int nf = 0; nf < 8; ++nf)
            #pragma unroll
            for (int q = 0; q < 4; ++q) acc[mi][nf][q] = 0.0f;

    auto load_stage = [&](int ic) {
        char* base = stg + (ic % STAGES) * STG_BYTES;
        char* ab = base;                 // A: 128 rows x 128B
        char* bb = base + BM * 128;      // B: 256 rows x 128B
        #pragma unroll
        for (int q = 0; q < 2; ++q) {    // A: 1024 chunks
            int idx = q * 512 + tid;
            int row = idx >> 3;
            int c   = idx & 7;
            cp_async16(ab + swz(row * 128 + c * 16),
                       g_A + (size_t)(bm0 + row) * K + ic * BK + c * 8);
        }
        #pragma unroll
        for (int q = 0; q < 4; ++q) {    // B: 2048 chunks
            int idx = q * 512 + tid;
            int row = idx >> 3;
            int c   = idx & 7;
            cp_async16(bb + swz(row * 128 + c * 16),
                       g_W + (size_t)row * K + ic * BK + c * 8);
        }
        CP_COMMIT();
    };

    load_stage(0);
    load_stage(1);
    load_stage(2);

    for (int ic = 0; ic < NCH; ++ic) {
        if (ic < NCH - 2)       { CP_WAIT(2); }
        else if (ic == NCH - 2) { CP_WAIT(1); }
        else                    { CP_WAIT(0); }
        __syncthreads();

        if (ic + 3 < NCH) load_stage(ic + 3);

        const char* base = stg + (ic % STAGES) * STG_BYTES;
        const char* as = base;
        const char* bs = base + BM * 128;

        #pragma unroll
        for (int ks = 0; ks < 4; ++ks) {
            const int k0 = ks * 16;
            uint32_t a[2][4];
            #pragma unroll
            for (int mi = 0; mi < 2; ++mi) {
                int row = wm + mi * 16 + (lane & 15);
                int cb  = k0 * 2 + (lane >> 4) * 16;
                uint32_t addr = (uint32_t)__cvta_generic_to_shared(
                    as + swz(row * 128 + cb));
                asm volatile(
                    "ldmatrix.sync.aligned.m8n8.x4.shared.b16 "
                    "{%0,%1,%2,%3}, [%4];"
                    : "=r"(a[mi][0]), "=r"(a[mi][1]),
                      "=r"(a[mi][2]), "=r"(a[mi][3])
                    : "r"(addr));
            }
            uint32_t b[4][4];
            #pragma unroll
            for (int ni = 0; ni < 4; ++ni) {
                int row = wn + ni * 16 + (lane & 7) + ((lane >> 4) << 3);
                int cb  = k0 * 2 + (((lane >> 3) & 1) << 4);
                uint32_t addr = (uint32_t)__cvta_generic_to_shared(
                    bs + swz(row * 128 + cb));
                asm volatile(
                    "ldmatrix.sync.aligned.m8n8.x4.shared.b16 "
                    "{%0,%1,%2,%3}, [%4];"
                    : "=r"(b[ni][0]), "=r"(b[ni][1]),
                      "=r"(b[ni][2]), "=r"(b[ni][3])
                    : "r"(addr));
            }
            #pragma unroll
            for (int mi = 0; mi < 2; ++mi)
                #pragma unroll
                for (int nf = 0; nf < 8; ++nf) {
                    const uint32_t b0 = b[nf >> 1][(nf & 1) * 2];
                    const uint32_t b1 = b[nf >> 1][(nf & 1) * 2 + 1];
                    asm volatile(
                        "mma.sync.aligned.m16n8k16.row.col.f32.f16.f16.f32 "
                        "{%0,%1,%2,%3}, {%4,%5,%6,%7}, {%8,%9}, {%0,%1,%2,%3};"
                        : "+f"(acc[mi][nf][0]), "+f"(acc[mi][nf][1]),
                          "+f"(acc[mi][nf][2]), "+f"(acc[mi][nf][3])
                        : "r"(a[mi][0]), "r"(a[mi][1]),
                          "r"(a[mi][2]), "r"(a[mi][3]),
                          "r"(b0), "r"(b1));
                }
        }
        __syncthreads();
    }

    // epilogue: + bias, float2 stores
    #pragma unroll
    for (int mi = 0; mi < 2; ++mi) {
        int r = bm0 + wm + mi * 16 + (lane >> 2);
        #pragma unroll
        for (int nf = 0; nf < 8; ++nf) {
            int cl = wn + nf * 8 + ((lane & 3) << 1);
            float b0 = bias_s[cl];
            float b1 = bias_s[cl + 1];
            float2 v0 = make_float2(acc[mi][nf][0] + b0, acc[mi][nf][1] + b1);
            float2 v1 = make_float2(acc[mi][nf][2] + b0, acc[mi][nf][3] + b1);
            *(float2*)(out + (size_t)r * OUT + cl) = v0;
            *(float2*)(out + (size_t)(r + 8) * OUT + cl) = v1;
        }
    }
}

// ---------------------------------------------------------------------------
static constexpr int GEMM_SMEM = 1024 + STAGES * STG_BYTES;   // ~193KB

extern "C" void kernel_launch(void* const* d_in, const int* in_sizes, int n_in,
                              void* d_out, int out_size) {
    const float* x     = (const float*)d_in[0];
    const float* grid  = (const float*)d_in[1];
    const float* coef  = (const float*)d_in[2];
    const float* scale = (const float*)d_in[3];
    const float* bias  = (const float*)d_in[4];
    float* out = (float*)d_out;

    const int B = in_sizes[0] / IN;

    cudaFuncSetAttribute(kan_gemm_kernel,
                         cudaFuncAttributeMaxDynamicSharedMemorySize,
                         GEMM_SMEM);

    init_kernel<<<1, 1>>>();
    minmax_kernel<<<2048, 256>>>((const float4*)x, in_sizes[0] / 4);
    prep_kernel<<<(OUT * K + 255) / 256, 256>>>(coef, scale);
    basis_kernel<<<B / 8, 256>>>(x, grid);

    kan_gemm_kernel<<<B / BM, 512, GEMM_SMEM>>>(bias, out);
}

// round 8
// speedup vs baseline: 1.4378x; 1.1185x over previous
#include <cuda_runtime.h>
#include <cuda_fp16.h>
#include <cstdint>

#define EPSF 1e-8f

static constexpr int IN  = 256;
static constexpr int OUT = 256;
static constexpr int G   = 5;
static constexpr int K   = IN * G;    // 1280
static constexpr int BQ  = 32768;

// GEMM tiling
static constexpr int BM = 128;
static constexpr int BN = 128;
static constexpr int BK = 64;         // halves per chunk = 128B rows
static constexpr int NCH = K / BK;    // 20
static constexpr int STAGES = 3;
static constexpr int STG_BYTES = (BM + BN) * 128;   // 32KB per stage

// K-permutation: k' = q*256 + l*8 + e, where original k = 40l + r, r = 8q + e.
// Basis lane l emits 40 halves (features 8l..8l+7, r = 5j+g); its q-th uint4
// lands at uint4 index q*32 + l of the row -> coalesced warp stores.
// W is written through the same permutation, so the GEMM is unchanged.

// ---------------- device globals (scratch; no allocations allowed) ----------
__device__ unsigned int g_min_u;
__device__ unsigned int g_max_u;
__device__ __half g_W[OUT * K];              // coef*scale fp16, permuted k
__device__ __half g_A[(size_t)BQ * K];       // basis fp16, permuted k

__device__ __forceinline__ unsigned int f2ord(float f) {
    unsigned int u = __float_as_uint(f);
    return (u & 0x80000000u) ? ~u : (u | 0x80000000u);
}
__device__ __forceinline__ float ord2f(unsigned int u) {
    unsigned int b = (u & 0x80000000u) ? (u & 0x7FFFFFFFu) : ~u;
    return __uint_as_float(b);
}

__device__ __forceinline__ void cp_async16(void* smem_dst, const void* gsrc) {
    uint32_t s = (uint32_t)__cvta_generic_to_shared(smem_dst);
    asm volatile("cp.async.cg.shared.global [%0], [%1], 16;\n"
                 :: "r"(s), "l"(gsrc));
}
#define CP_COMMIT() asm volatile("cp.async.commit_group;\n" ::: "memory")
#define CP_WAIT(n)  asm volatile("cp.async.wait_group %0;\n" :: "n"(n) : "memory")

// XOR swizzle for 128-byte rows, conflict-free ldmatrix
__device__ __forceinline__ uint32_t swz(uint32_t b) {
    return b ^ ((b >> 3) & 0x70);
}

// ---------------- kernel 0: reset reduction state ---------------------------
__global__ void init_kernel() {
    g_min_u = 0xFFFFFFFFu;
    g_max_u = 0x00000000u;
}

// ---------------- kernel 1: global min/max of x -----------------------------
__global__ void minmax_kernel(const float4* __restrict__ x4, int n4) {
    float lmin =  3.4e38f;
    float lmax = -3.4e38f;
    for (int i = blockIdx.x * blockDim.x + threadIdx.x; i < n4;
         i += gridDim.x * blockDim.x) {
        float4 v = x4[i];
        lmin = fminf(lmin, fminf(fminf(v.x, v.y), fminf(v.z, v.w)));
        lmax = fmaxf(lmax, fmaxf(fmaxf(v.x, v.y), fmaxf(v.z, v.w)));
    }
    #pragma unroll
    for (int off = 16; off > 0; off >>= 1) {
        lmin = fminf(lmin, __shfl_xor_sync(0xFFFFFFFFu, lmin, off));
        lmax = fmaxf(lmax, __shfl_xor_sync(0xFFFFFFFFu, lmax, off));
    }
    __shared__ float smin[8], smax[8];
    int warp = threadIdx.x >> 5, lane = threadIdx.x & 31;
    if (lane == 0) { smin[warp] = lmin; smax[warp] = lmax; }
    __syncthreads();
    if (warp == 0) {
        int nw = blockDim.x >> 5;
        lmin = (lane < nw) ? smin[lane] :  3.4e38f;
        lmax = (lane < nw) ? smax[lane] : -3.4e38f;
        #pragma unroll
        for (int off = 4; off > 0; off >>= 1) {
            lmin = fminf(lmin, __shfl_xor_sync(0xFFFFFFFFu, lmin, off));
            lmax = fmaxf(lmax, __shfl_xor_sync(0xFFFFFFFFu, lmax, off));
        }
        if (lane == 0) {
            atomicMin(&g_min_u, f2ord(lmin));
            atomicMax(&g_max_u, f2ord(lmax));
        }
    }
}

// ---------------- kernel 2: W = coef * scale -> fp16, permuted k ------------
// idx = o*K + k'; decode k' -> (i, g); gather-read coef, coalesced write.
__global__ void prep_kernel(const float* __restrict__ coef,
                            const float* __restrict__ scale) {
    int idx = blockIdx.x * blockDim.x + threadIdx.x;
    if (idx < OUT * K) {
        int o   = idx / K;
        int kp  = idx % K;
        int q   = kp >> 8;          // 0..4
        int rem = kp & 255;
        int l   = rem >> 3;         // 0..31
        int e   = rem & 7;
        int r   = q * 8 + e;        // 0..39
        int j   = r / G;
        int g   = r % G;
        int i   = l * 8 + j;
        g_W[idx] = __float2half(coef[o * K + i * G + g] * scale[o * IN + i]);
    }
}

// ---------------- kernel 3: basis(x) -> g_A, coalesced via permutation ------
// warp handles one row; lane computes features 8l..8l+7 -> 40 halves;
// q-th uint4 stored at uint4 index q*32+lane of the row (coalesced).
__global__ __launch_bounds__(256)
void basis_kernel(const float* __restrict__ x, const float* __restrict__ grid) {
    const int warp = threadIdx.x >> 5, lane = threadIdx.x & 31;
    const int row = blockIdx.x * 8 + warp;

    float gr[G];
    #pragma unroll
    for (int g = 0; g < G; ++g) gr[g] = __ldg(grid + g);

    const float xmin = ord2f(g_min_u);
    const float xmax = ord2f(g_max_u);
    const float s2 = 2.0f / (xmax - xmin + EPSF);

    const float4* xr = (const float4*)(x + (size_t)row * IN + lane * 8);
    float4 v0 = xr[0], v1 = xr[1];
    float xs[8] = {v0.x, v0.y, v0.z, v0.w, v1.x, v1.y, v1.z, v1.w};

    union { __half h[40]; uint4 u[5]; } buf;
    #pragma unroll
    for (int j = 0; j < 8; ++j) {
        float xn = (xs[j] - xmin) * s2 - 1.0f;
        float bb[G];
        float bsum = 0.0f;
        #pragma unroll
        for (int g = 0; g < G; ++g) {
            float d = fabsf(xn - gr[g]);
            float v = (d < 1.0f) ? (1.0f - d * d * d) : 0.0f;
            bb[g] = v;
            bsum += v;
        }
        float inv = 1.0f / (bsum + EPSF);
        #pragma unroll
        for (int g = 0; g < G; ++g)
            buf.h[j * G + g] = __float2half(bb[g] * inv);
    }
    uint4* gdst = (uint4*)(g_A + (size_t)row * K);
    #pragma unroll
    for (int q = 0; q < 5; ++q) gdst[q * 32 + lane] = buf.u[q];
}

// ---------------- kernel 4: fp16 GEMM, 256 thr, occ 2, single barrier -------
// C[b][o] = sum_k A[b][k] * W[o][k] + bias[o]
// 8 warps, warp tile 32x64: wm = (warp>>1)*32, wn = (warp&1)*64
__global__ __launch_bounds__(256, 2)
void kan_gemm_kernel(const float* __restrict__ bias, float* __restrict__ out) {
    extern __shared__ __align__(16) char smem_raw[];
    float* bias_s = (float*)smem_raw;              // 128 floats
    char* stg = smem_raw + 1024;                   // STAGES x 32KB

    const int tid = threadIdx.x;
    const int bm0 = blockIdx.y * BM;
    const int bn0 = blockIdx.x * BN;

    if (tid < BN) bias_s[tid] = bias[bn0 + tid];

    const int warp = tid >> 5, lane = tid & 31;
    const int wm = (warp >> 1) * 32;
    const int wn = (warp & 1) * 64;

    float acc[2][8][4];
    #pragma unroll
    for (int mi = 0; mi < 2; ++mi)
        #pragma unroll
        for (int nf = 0; nf < 8; ++nf)
            #pragma unroll
            for (int q = 0; q < 4; ++q) acc[mi][nf][q] = 0.0f;

    auto load_stage = [&](int ic) {
        char* base = stg + (ic % STAGES) * STG_BYTES;
        char* ab = base;                 // A: 128 rows x 128B
        char* bb = base + BM * 128;      // B: 128 rows x 128B
        #pragma unroll
        for (int q = 0; q < 4; ++q) {
            int idx = q * 256 + tid;     // 0..1023
            int row = idx >> 3;
            int c   = idx & 7;
            uint32_t so = swz(row * 128 + c * 16);
            cp_async16(ab + so,
                       g_A + (size_t)(bm0 + row) * K + ic * BK + c * 8);
            cp_async16(bb + so,
                       g_W + (size_t)(bn0 + row) * K + ic * BK + c * 8);
        }
        CP_COMMIT();
    };

    load_stage(0);
    load_stage(1);

    for (int ic = 0; ic < NCH; ++ic) {
        if (ic == NCH - 1) { CP_WAIT(0); } else { CP_WAIT(1); }
        __syncthreads();
        // single barrier per iter: load below targets buffer of chunk ic-1,
        // whose MMAs all warps completed before this barrier.
        if (ic + 2 < NCH) load_stage(ic + 2);

        const char* base = stg + (ic % STAGES) * STG_BYTES;
        const char* as = base;
        const char* bs = base + BM * 128;

        #pragma unroll
        for (int ks = 0; ks < 4; ++ks) {
            const int k0 = ks * 16;
            uint32_t a[2][4];
            #pragma unroll
            for (int mi = 0; mi < 2; ++mi) {
                int row = wm + mi * 16 + (lane & 15);
                int cb  = k0 * 2 + (lane >> 4) * 16;
                uint32_t addr = (uint32_t)__cvta_generic_to_shared(
                    as + swz(row * 128 + cb));
                asm volatile(
                    "ldmatrix.sync.aligned.m8n8.x4.shared.b16 "
                    "{%0,%1,%2,%3}, [%4];"
                    : "=r"(a[mi][0]), "=r"(a[mi][1]),
                      "=r"(a[mi][2]), "=r"(a[mi][3])
                    : "r"(addr));
            }
            uint32_t b[4][4];
            #pragma unroll
            for (int ni = 0; ni < 4; ++ni) {
                int row = wn + ni * 16 + (lane & 7) + ((lane >> 4) << 3);
                int cb  = k0 * 2 + (((lane >> 3) & 1) << 4);
                uint32_t addr = (uint32_t)__cvta_generic_to_shared(
                    bs + swz(row * 128 + cb));
                asm volatile(
                    "ldmatrix.sync.aligned.m8n8.x4.shared.b16 "
                    "{%0,%1,%2,%3}, [%4];"
                    : "=r"(b[ni][0]), "=r"(b[ni][1]),
                      "=r"(b[ni][2]), "=r"(b[ni][3])
                    : "r"(addr));
            }
            #pragma unroll
            for (int mi = 0; mi < 2; ++mi)
                #pragma unroll
                for (int nf = 0; nf < 8; ++nf) {
                    const uint32_t b0 = b[nf >> 1][(nf & 1) * 2];
                    const uint32_t b1 = b[nf >> 1][(nf & 1) * 2 + 1];
                    asm volatile(
                        "mma.sync.aligned.m16n8k16.row.col.f32.f16.f16.f32 "
                        "{%0,%1,%2,%3}, {%4,%5,%6,%7}, {%8,%9}, {%0,%1,%2,%3};"
                        : "+f"(acc[mi][nf][0]), "+f"(acc[mi][nf][1]),
                          "+f"(acc[mi][nf][2]), "+f"(acc[mi][nf][3])
                        : "r"(a[mi][0]), "r"(a[mi][1]),
                          "r"(a[mi][2]), "r"(a[mi][3]),
                          "r"(b0), "r"(b1));
                }
        }
    }

    // epilogue: + bias, float2 stores
    #pragma unroll
    for (int mi = 0; mi < 2; ++mi) {
        int r = bm0 + wm + mi * 16 + (lane >> 2);
        #pragma unroll
        for (int nf = 0; nf < 8; ++nf) {
            int cl = wn + nf * 8 + ((lane & 3) << 1);
            int c = bn0 + cl;
            float b0 = bias_s[cl];
            float b1 = bias_s[cl + 1];
            float2 v0 = make_float2(acc[mi][nf][0] + b0, acc[mi][nf][1] + b1);
            float2 v1 = make_float2(acc[mi][nf][2] + b0, acc[mi][nf][3] + b1);
            *(float2*)(out + (size_t)r * OUT + c) = v0;
            *(float2*)(out + (size_t)(r + 8) * OUT + c) = v1;
        }
    }
}

// ---------------------------------------------------------------------------
static constexpr int GEMM_SMEM = 1024 + STAGES * STG_BYTES;   // ~97KB

extern "C" void kernel_launch(void* const* d_in, const int* in_sizes, int n_in,
                              void* d_out, int out_size) {
    const float* x     = (const float*)d_in[0];
    const float* grid  = (const float*)d_in[1];
    const float* coef  = (const float*)d_in[2];
    const float* scale = (const float*)d_in[3];
    const float* bias  = (const float*)d_in[4];
    float* out = (float*)d_out;

    const int B = in_sizes[0] / IN;

    cudaFuncSetAttribute(kan_gemm_kernel,
                         cudaFuncAttributeMaxDynamicSharedMemorySize,
                         GEMM_SMEM);

    init_kernel<<<1, 1>>>();
    minmax_kernel<<<2048, 256>>>((const float4*)x, in_sizes[0] / 4);
    prep_kernel<<<(OUT * K + 255) / 256, 256>>>(coef, scale);
    basis_kernel<<<B / 8, 256>>>(x, grid);

    dim3 g(OUT / BN, B / BM);
    kan_gemm_kernel<<<g, 256, GEMM_SMEM>>>(bias, out);
}